// round 8
// baseline (speedup 1.0000x reference)
#include <cuda_runtime.h>
#include <cuda_fp16.h>
#include <stdint.h>

// Conv 3x3 s1 p1, NCHW fp32: x[32,128,56,56] * w[256,128,3,3] + bias -> out[32,256,56,56]
// fp16 implicit GEMM on mma.sync.m16n8k16 (fp32 accum).
// Persistent CTAs + atomic tile stealing; 3-stage cp.async ring; one sync per k-step.

#define N_IMG 32
#define C_IN  128
#define HW    56
#define PIX   3136              // 56*56
#define K_OUT 256
#define NPIX  100352            // 32*3136
#define BM    128               // out-channels per tile
#define BN    128               // pixels per tile
#define NKT   18                // K steps: 9 (r,s) x 2 c-halves of 64
#define NTHREADS 256
#define NTILES ((NPIX / BN) * (K_OUT / BM))   // 784 * 2 = 1568
#define NCTAS  304                            // 2 per SM (152 SMs)

// ---------------- scratch (device globals; no allocs allowed) ----------------
__device__ __align__(16) __half g_xt[(size_t)NPIX * C_IN];   // NHWC fp16
__device__ __align__(16) __half g_w[NKT * 256 * 64];         // [kt][m][c64] fp16
__device__ unsigned g_tile_ctr;

// ---------------- helpers ----------------
__device__ __forceinline__ uint32_t smem_u32(const void* p) {
    uint32_t a;
    asm("{ .reg .u64 t; cvta.to.shared.u64 t, %1; cvt.u32.u64 %0, t; }" : "=r"(a) : "l"(p));
    return a;
}
__device__ __forceinline__ uint32_t sw128(uint32_t off) { return off ^ ((off >> 3) & 0x70); }

__device__ __forceinline__ void cp16(uint32_t dst, const void* src, int src_sz) {
    asm volatile("cp.async.cg.shared.global [%0], [%1], 16, %2;"
                 :: "r"(dst), "l"(src), "r"(src_sz) : "memory");
}
__device__ __forceinline__ void ldsm4(uint32_t* r, uint32_t a) {
    asm volatile("ldmatrix.sync.aligned.m8n8.x4.shared.b16 {%0,%1,%2,%3}, [%4];"
                 : "=r"(r[0]), "=r"(r[1]), "=r"(r[2]), "=r"(r[3]) : "r"(a));
}
__device__ __forceinline__ void mma_fp16(float* c, const uint32_t* a, const uint32_t* b) {
    asm volatile(
        "mma.sync.aligned.m16n8k16.row.col.f32.f16.f16.f32 "
        "{%0,%1,%2,%3}, {%4,%5,%6,%7}, {%8,%9}, {%0,%1,%2,%3};"
        : "+f"(c[0]), "+f"(c[1]), "+f"(c[2]), "+f"(c[3])
        : "r"(a[0]), "r"(a[1]), "r"(a[2]), "r"(a[3]), "r"(b[0]), "r"(b[1]));
}

// ---------------- smem: 3-stage ring, 32 KB/stage: A 16K | B 16K ----------------
#define STAGE_BYTES 32768
#define A_OFF(st) ((st) * STAGE_BYTES)
#define B_OFF(st) ((st) * STAGE_BYTES + 16384)
#define SMEM_TOTAL (3 * STAGE_BYTES)

// ---------------- prep kernels ----------------
__global__ void reset_kernel() { g_tile_ctr = 0; }

__global__ void wprep_kernel(const float* __restrict__ w) {
    int idx = blockIdx.x * 256 + threadIdx.x;     // < 256*1152
    int m = idx / 1152;
    int k = idx - m * 1152;
    int c = k / 9;
    int rs = k - c * 9;
    int kt = rs * 2 + (c >> 6);
    g_w[(kt * 256 + m) * 64 + (c & 63)] = __float2half(w[idx]);
}

__global__ void xprep_kernel(const float* __restrict__ x) {
    __shared__ float t[32][33];
    const int n  = blockIdx.z;
    const int c0 = blockIdx.y * 32;
    const int p0 = blockIdx.x * 32;
    const int tx = threadIdx.x, ty = threadIdx.y;   // 32 x 8
    const float* src = x + ((size_t)n * C_IN + c0) * PIX + p0;
#pragma unroll
    for (int i = 0; i < 4; ++i) {
        int c = ty + i * 8;
        t[c][tx] = src[(size_t)c * PIX + tx];
    }
    __syncthreads();
#pragma unroll
    for (int i = 0; i < 4; ++i) {
        int pr = ty + i * 8;
        g_xt[((size_t)n * PIX + p0 + pr) * C_IN + c0 + tx] = __float2half(t[tx][pr]);
    }
}

// ---------------- main conv kernel (persistent) ----------------
__global__ __launch_bounds__(NTHREADS, 2)
void conv_mma_fp16_kernel(const float* __restrict__ bias, float* __restrict__ out) {
    extern __shared__ char smem[];
    __shared__ unsigned s_tile;
    const uint32_t sbase = smem_u32(smem);
    const int tid = threadIdx.x;
    const int wid = tid >> 5;
    const int l   = tid & 31;
    const int wy = wid & 1;            // M half (64 rows)
    const int wx = wid >> 1;           // N quarter (32 pixels)

    // tile-independent per-thread constants
    const int brow = tid >> 1;          // 0..127 (B pixel row)
    const int bhr  = tid & 1;           // half-row (64B)
    const int a_m       = wy * 64 + (l & 15);
    const uint32_t a_kb = (uint32_t)(l >> 4) * 16;
    const int b_n       = wx * 32 + (l & 7) + ((l >> 4) << 3);
    const uint32_t b_kb = (uint32_t)((l >> 3) & 1) * 16;

    for (;;) {
        if (tid == 0) s_tile = atomicAdd(&g_tile_ctr, 1u);
        __syncthreads();                 // broadcast tile; also fences prev-tile smem reads
        const unsigned tile = s_tile;
        if (tile >= NTILES) break;

        const int pixBase = (int)(tile >> 1) * BN;   // mTile fastest -> B reuse in L2
        const int mBase   = (int)(tile & 1) * BM;

        // per-tile B-row geometry
        const int p    = pixBase + brow;
        const int bn   = p / PIX;
        const int brem = p - bn * PIX;
        const int bh   = brem / HW;
        const int bw   = brem - bh * HW;
        const size_t bimg = (size_t)bn * PIX;

        auto issue = [&](int kt) {
            const int st = kt % 3;
            const uint4* wsrc = (const uint4*)g_w + (size_t)(kt * 256 + mBase) * 8;
#pragma unroll
            for (int j = 0; j < 4; ++j) {
                int i = j * 256 + tid;
                uint32_t dst = sbase + A_OFF(st) +
                               sw128((uint32_t)((i >> 3) * 128 + (i & 7) * 16));
                cp16(dst, wsrc + i, 16);
            }
            const int rs = kt >> 1, chalf = kt & 1;
            const int r = rs / 3, s = rs - r * 3;
            const int ih = bh + r - 1, iw = bw + s - 1;
            const bool valid = ((unsigned)ih < (unsigned)HW) && ((unsigned)iw < (unsigned)HW);
            const size_t eb = valid
                ? ((bimg + (size_t)ih * HW + iw) * C_IN + chalf * 64 + bhr * 32) : 0;
            const int ssz = valid ? 16 : 0;
            const uint4* bsrc = (const uint4*)(g_xt + eb);
#pragma unroll
            for (int j = 0; j < 4; ++j) {
                uint32_t dst = sbase + B_OFF(st) +
                               sw128((uint32_t)(brow * 128 + bhr * 64 + j * 16));
                cp16(dst, bsrc + j, ssz);
            }
            asm volatile("cp.async.commit_group;" ::: "memory");
        };

        float acc[4][4][4];
#pragma unroll
        for (int i = 0; i < 4; ++i)
#pragma unroll
            for (int j = 0; j < 4; ++j)
#pragma unroll
                for (int q = 0; q < 4; ++q)
                    acc[i][j][q] = 0.0f;

        issue(0);
        issue(1);

        for (int kt = 0; kt < NKT; ++kt) {
            const int st = kt % 3;
            if (kt == NKT - 1) asm volatile("cp.async.wait_group 0;" ::: "memory");
            else               asm volatile("cp.async.wait_group 1;" ::: "memory");
            __syncthreads();               // single sync per k-step (ring analysis: trailing sync redundant)
            if (kt + 2 < NKT) issue(kt + 2);

            const uint32_t aB = sbase + A_OFF(st);
            const uint32_t bB = sbase + B_OFF(st);

#pragma unroll
            for (int k16 = 0; k16 < 4; ++k16) {
                uint32_t af[4][4], bf[2][4];
                const uint32_t kb = (uint32_t)k16 * 32;
#pragma unroll
                for (int mt = 0; mt < 4; ++mt)
                    ldsm4(af[mt], aB + sw128((uint32_t)((a_m + mt * 16) * 128) + kb + a_kb));
#pragma unroll
                for (int np = 0; np < 2; ++np)
                    ldsm4(bf[np], bB + sw128((uint32_t)((b_n + np * 16) * 128) + kb + b_kb));
#pragma unroll
                for (int mt = 0; mt < 4; ++mt)
#pragma unroll
                    for (int nt = 0; nt < 4; ++nt)
                        mma_fp16(acc[mt][nt], af[mt], &bf[nt >> 1][(nt & 1) * 2]);
            }
        }

        // epilogue: C frag -> NCHW out (+bias); 8-pixel groups stay in-image (8|3136)
#pragma unroll
        for (int mt = 0; mt < 4; ++mt) {
            const int ch0 = mBase + wy * 64 + mt * 16 + (l >> 2);
            const float bv0 = __ldg(&bias[ch0]);
            const float bv1 = __ldg(&bias[ch0 + 8]);
#pragma unroll
            for (int nt = 0; nt < 4; ++nt) {
                const int p0  = pixBase + wx * 32 + nt * 8 + (l & 3) * 2;
                const int on  = p0 / PIX;
                const int pin = p0 - on * PIX;
                float* o = out + ((size_t)on * K_OUT + ch0) * PIX + pin;
                float2 v0, v1;
                v0.x = acc[mt][nt][0] + bv0; v0.y = acc[mt][nt][1] + bv0;
                v1.x = acc[mt][nt][2] + bv1; v1.y = acc[mt][nt][3] + bv1;
                *(float2*)o             = v0;
                *(float2*)(o + 8 * PIX) = v1;
            }
        }
    }
}

// ---------------- launch ----------------
extern "C" void kernel_launch(void* const* d_in, const int* in_sizes, int n_in,
                              void* d_out, int out_size) {
    const float* x    = (const float*)d_in[0];
    const float* wgt  = (const float*)d_in[1];
    const float* bias = (const float*)d_in[2];
    float* out        = (float*)d_out;

    cudaFuncSetAttribute(conv_mma_fp16_kernel,
                         cudaFuncAttributeMaxDynamicSharedMemorySize, SMEM_TOTAL);

    reset_kernel<<<1, 1>>>();
    wprep_kernel<<<(256 * 1152) / 256, 256>>>(wgt);
    {
        dim3 g(PIX / 32, C_IN / 32, N_IMG);   // (98, 4, 32)
        dim3 b(32, 8);
        xprep_kernel<<<g, b>>>(x);
    }
    conv_mma_fp16_kernel<<<NCTAS, NTHREADS, SMEM_TOTAL>>>(bias, out);
}

// round 9
// speedup vs baseline: 1.0099x; 1.0099x over previous
#include <cuda_runtime.h>
#include <cuda_fp16.h>
#include <stdint.h>

// Conv 3x3 s1 p1, NCHW fp32: x[32,128,56,56] * w[256,128,3,3] + bias -> out[32,256,56,56]
// fp16 implicit GEMM on mma.sync.m16n8k16 (fp32 accum).
// Occupancy-3 variant: BM=64, BN=128, warp tile 32x32, 3-stage x 24KB ring, <=85 regs.

#define N_IMG 32
#define C_IN  128
#define HW    56
#define PIX   3136              // 56*56
#define K_OUT 256
#define NPIX  100352            // 32*3136
#define BM    64                // out-channels per CTA
#define BN    128               // pixels per CTA
#define NKT   18                // K steps: 9 (r,s) x 2 c-halves of 64
#define NTHREADS 256

// ---------------- scratch (device globals; no allocs allowed) ----------------
__device__ __align__(16) __half g_xt[(size_t)NPIX * C_IN];   // NHWC fp16
__device__ __align__(16) __half g_w[NKT * 256 * 64];         // [kt][m][c64] fp16

// ---------------- helpers ----------------
__device__ __forceinline__ uint32_t smem_u32(const void* p) {
    uint32_t a;
    asm("{ .reg .u64 t; cvta.to.shared.u64 t, %1; cvt.u32.u64 %0, t; }" : "=r"(a) : "l"(p));
    return a;
}
__device__ __forceinline__ uint32_t sw128(uint32_t off) { return off ^ ((off >> 3) & 0x70); }

__device__ __forceinline__ void cp16(uint32_t dst, const void* src, int src_sz) {
    asm volatile("cp.async.cg.shared.global [%0], [%1], 16, %2;"
                 :: "r"(dst), "l"(src), "r"(src_sz) : "memory");
}
__device__ __forceinline__ void ldsm4(uint32_t* r, uint32_t a) {
    asm volatile("ldmatrix.sync.aligned.m8n8.x4.shared.b16 {%0,%1,%2,%3}, [%4];"
                 : "=r"(r[0]), "=r"(r[1]), "=r"(r[2]), "=r"(r[3]) : "r"(a));
}
__device__ __forceinline__ void mma_fp16(float* c, const uint32_t* a, const uint32_t* b) {
    asm volatile(
        "mma.sync.aligned.m16n8k16.row.col.f32.f16.f16.f32 "
        "{%0,%1,%2,%3}, {%4,%5,%6,%7}, {%8,%9}, {%0,%1,%2,%3};"
        : "+f"(c[0]), "+f"(c[1]), "+f"(c[2]), "+f"(c[3])
        : "r"(a[0]), "r"(a[1]), "r"(a[2]), "r"(a[3]), "r"(b[0]), "r"(b[1]));
}

// ---------------- smem: 3-stage ring, 24 KB/stage: A 8K | B 16K ----------------
#define STAGE_BYTES 24576
#define A_OFF(st) ((st) * STAGE_BYTES)
#define B_OFF(st) ((st) * STAGE_BYTES + 8192)
#define SMEM_TOTAL (3 * STAGE_BYTES)

// ---------------- prep kernels ----------------
__global__ void wprep_kernel(const float* __restrict__ w) {
    int idx = blockIdx.x * 256 + threadIdx.x;     // < 256*1152
    int m = idx / 1152;
    int k = idx - m * 1152;
    int c = k / 9;
    int rs = k - c * 9;
    int kt = rs * 2 + (c >> 6);
    g_w[(kt * 256 + m) * 64 + (c & 63)] = __float2half(w[idx]);
}

__global__ void xprep_kernel(const float* __restrict__ x) {
    __shared__ float t[32][33];
    const int n  = blockIdx.z;
    const int c0 = blockIdx.y * 32;
    const int p0 = blockIdx.x * 32;
    const int tx = threadIdx.x, ty = threadIdx.y;   // 32 x 8
    const float* src = x + ((size_t)n * C_IN + c0) * PIX + p0;
#pragma unroll
    for (int i = 0; i < 4; ++i) {
        int c = ty + i * 8;
        t[c][tx] = src[(size_t)c * PIX + tx];
    }
    __syncthreads();
#pragma unroll
    for (int i = 0; i < 4; ++i) {
        int pr = ty + i * 8;
        g_xt[((size_t)n * PIX + p0 + pr) * C_IN + c0 + tx] = __float2half(t[tx][pr]);
    }
}

// ---------------- main conv kernel ----------------
__global__ __launch_bounds__(NTHREADS, 3)
void conv_mma_fp16_kernel(const float* __restrict__ bias, float* __restrict__ out) {
    extern __shared__ char smem[];
    const uint32_t sbase = smem_u32(smem);
    const int tid = threadIdx.x;
    const int wid = tid >> 5;
    const int l   = tid & 31;
    const int pixBase = blockIdx.x * BN;
    const int mBase   = blockIdx.y * BM;
    const int wy = wid & 1;            // M half (32 rows)
    const int wx = wid >> 1;           // N quarter (32 pixels)

    // ---- per-thread B-row geometry: thread pair owns pixel row tid>>1 ----
    const int brow = tid >> 1;          // 0..127
    const int bhr  = tid & 1;           // half-row (64B)
    const int p    = pixBase + brow;
    const int bn   = p / PIX;
    const int brem = p - bn * PIX;
    const int bh   = brem / HW;
    const int bw   = brem - bh * HW;
    const size_t bimg = (size_t)bn * PIX;

    // ---- async stage issue ----
    auto issue = [&](int kt) {
        const int st = kt % 3;
        // A: weights [kt][mBase..mBase+63][64] = 8KB -> 512 uint4 (2 per thread)
        const uint4* wsrc = (const uint4*)g_w + (size_t)(kt * 256 + mBase) * 8;
#pragma unroll
        for (int j = 0; j < 2; ++j) {
            int i = j * 256 + tid;
            uint32_t dst = sbase + A_OFF(st) + sw128((uint32_t)((i >> 3) * 128 + (i & 7) * 16));
            cp16(dst, wsrc + i, 16);
        }
        // B: im2col row (64 ch = 128B); thread pair covers one row, zero-fill OOB
        const int rs = kt >> 1, chalf = kt & 1;
        const int r = rs / 3, s = rs - r * 3;
        const int ih = bh + r - 1, iw = bw + s - 1;
        const bool valid = ((unsigned)ih < (unsigned)HW) && ((unsigned)iw < (unsigned)HW);
        const size_t eb = valid ? ((bimg + (size_t)ih * HW + iw) * C_IN + chalf * 64 + bhr * 32)
                                : 0;
        const int ssz = valid ? 16 : 0;
        const uint4* bsrc = (const uint4*)(g_xt + eb);
#pragma unroll
        for (int j = 0; j < 4; ++j) {
            uint32_t dst = sbase + B_OFF(st) +
                           sw128((uint32_t)(brow * 128 + bhr * 64 + j * 16));
            cp16(dst, bsrc + j, ssz);
        }
        asm volatile("cp.async.commit_group;" ::: "memory");
    };

    float acc[2][4][4];
#pragma unroll
    for (int i = 0; i < 2; ++i)
#pragma unroll
        for (int j = 0; j < 4; ++j)
#pragma unroll
            for (int q = 0; q < 4; ++q)
                acc[i][j][q] = 0.0f;

    issue(0);
    issue(1);

    // fragment lane addressing (ldmatrix x4 canonical, validated)
    const int a_m       = wy * 32 + (l & 15);
    const uint32_t a_kb = (uint32_t)(l >> 4) * 16;
    const int b_n       = wx * 32 + (l & 7) + ((l >> 4) << 3);
    const uint32_t b_kb = (uint32_t)((l >> 3) & 1) * 16;

    for (int kt = 0; kt < NKT; ++kt) {
        const int st = kt % 3;
        if (kt == NKT - 1) asm volatile("cp.async.wait_group 0;" ::: "memory");
        else               asm volatile("cp.async.wait_group 1;" ::: "memory");
        __syncthreads();               // single sync per k-step (ring analysis: trailing sync redundant)
        if (kt + 2 < NKT) issue(kt + 2);   // overlaps with compute below

        const uint32_t aB = sbase + A_OFF(st);
        const uint32_t bB = sbase + B_OFF(st);

#pragma unroll
        for (int k16 = 0; k16 < 4; ++k16) {
            uint32_t af[2][4], bf[2][4];
            const uint32_t kb = (uint32_t)k16 * 32;
#pragma unroll
            for (int mt = 0; mt < 2; ++mt)
                ldsm4(af[mt], aB + sw128((uint32_t)((a_m + mt * 16) * 128) + kb + a_kb));
#pragma unroll
            for (int np = 0; np < 2; ++np)
                ldsm4(bf[np], bB + sw128((uint32_t)((b_n + np * 16) * 128) + kb + b_kb));
#pragma unroll
            for (int mt = 0; mt < 2; ++mt)
#pragma unroll
                for (int nt = 0; nt < 4; ++nt)
                    mma_fp16(acc[mt][nt], af[mt], &bf[nt >> 1][(nt & 1) * 2]);
        }
    }

    // ---- epilogue: C frag -> NCHW out (+bias). 8-pixel groups stay in-image. ----
#pragma unroll
    for (int mt = 0; mt < 2; ++mt) {
        const int ch0 = mBase + wy * 32 + mt * 16 + (l >> 2);
        const float bv0 = __ldg(&bias[ch0]);
        const float bv1 = __ldg(&bias[ch0 + 8]);
#pragma unroll
        for (int nt = 0; nt < 4; ++nt) {
            const int p0  = pixBase + wx * 32 + nt * 8 + (l & 3) * 2;
            const int on  = p0 / PIX;
            const int pin = p0 - on * PIX;
            float* o = out + ((size_t)on * K_OUT + ch0) * PIX + pin;
            float2 v0, v1;
            v0.x = acc[mt][nt][0] + bv0; v0.y = acc[mt][nt][1] + bv0;
            v1.x = acc[mt][nt][2] + bv1; v1.y = acc[mt][nt][3] + bv1;
            *(float2*)o             = v0;
            *(float2*)(o + 8 * PIX) = v1;
        }
    }
}

// ---------------- launch ----------------
extern "C" void kernel_launch(void* const* d_in, const int* in_sizes, int n_in,
                              void* d_out, int out_size) {
    const float* x    = (const float*)d_in[0];
    const float* wgt  = (const float*)d_in[1];
    const float* bias = (const float*)d_in[2];
    float* out        = (float*)d_out;

    cudaFuncSetAttribute(conv_mma_fp16_kernel,
                         cudaFuncAttributeMaxDynamicSharedMemorySize, SMEM_TOTAL);

    wprep_kernel<<<(256 * 1152) / 256, 256>>>(wgt);
    {
        dim3 g(PIX / 32, C_IN / 32, N_IMG);   // (98, 4, 32)
        dim3 b(32, 8);
        xprep_kernel<<<g, b>>>(x);
    }
    conv_mma_fp16_kernel<<<dim3(NPIX / BN, K_OUT / BM), NTHREADS, SMEM_TOTAL>>>(bias, out);
}

// round 10
// speedup vs baseline: 1.1028x; 1.0919x over previous
#include <cuda_runtime.h>
#include <cuda_fp16.h>
#include <stdint.h>

// Conv 3x3 s1 p1, NCHW fp32: x[32,128,56,56] * w[256,128,3,3] + bias -> out[32,256,56,56]
// fp16 implicit GEMM on mma.sync.m16n8k16 (fp32 accum).
// A (weights) pre-arranged fragment-major -> LDG.128 direct to registers (no smem).
// B (im2col) via 3-stage cp.async ring. occ 2, warp tile 64x32.

#define N_IMG 32
#define C_IN  128
#define HW    56
#define PIX   3136              // 56*56
#define K_OUT 256
#define NPIX  100352            // 32*3136
#define BM    128               // out-channels per CTA
#define BN    128               // pixels per CTA
#define NKT   18                // K steps: 9 (r,s) x 2 c-halves of 64
#define NTHREADS 256

// ---------------- scratch (device globals; no allocs allowed) ----------------
__device__ __align__(16) __half g_xt[(size_t)NPIX * C_IN];   // NHWC fp16
// A fragments: [kt][mt16(0..15)][k16(0..3)][lane(0..31)] -> uint4 = regs a0..a3
__device__ __align__(16) uint4 g_wf[NKT * 16 * 4 * 32];      // 36864 * 16B

// ---------------- helpers ----------------
__device__ __forceinline__ uint32_t smem_u32(const void* p) {
    uint32_t a;
    asm("{ .reg .u64 t; cvta.to.shared.u64 t, %1; cvt.u32.u64 %0, t; }" : "=r"(a) : "l"(p));
    return a;
}
__device__ __forceinline__ uint32_t sw128(uint32_t off) { return off ^ ((off >> 3) & 0x70); }

__device__ __forceinline__ void cp16(uint32_t dst, const void* src, int src_sz) {
    asm volatile("cp.async.cg.shared.global [%0], [%1], 16, %2;"
                 :: "r"(dst), "l"(src), "r"(src_sz) : "memory");
}
__device__ __forceinline__ void ldsm4(uint32_t* r, uint32_t a) {
    asm volatile("ldmatrix.sync.aligned.m8n8.x4.shared.b16 {%0,%1,%2,%3}, [%4];"
                 : "=r"(r[0]), "=r"(r[1]), "=r"(r[2]), "=r"(r[3]) : "r"(a));
}
__device__ __forceinline__ void mma_fp16(float* c, const uint32_t* a, const uint32_t* b) {
    asm volatile(
        "mma.sync.aligned.m16n8k16.row.col.f32.f16.f16.f32 "
        "{%0,%1,%2,%3}, {%4,%5,%6,%7}, {%8,%9}, {%0,%1,%2,%3};"
        : "+f"(c[0]), "+f"(c[1]), "+f"(c[2]), "+f"(c[3])
        : "r"(a[0]), "r"(a[1]), "r"(a[2]), "r"(a[3]), "r"(b[0]), "r"(b[1]));
}

// ---------------- smem: 3-stage ring, B only, 16 KB/stage ----------------
#define STAGE_BYTES 16384
#define B_OFF(st) ((st) * STAGE_BYTES)
#define SMEM_TOTAL (3 * STAGE_BYTES)

// ---------------- prep kernels ----------------
// Emit A fragments in mma.m16n8k16 row-major A layout:
//   lane l: g = l>>2, c0 = (l&3)*2
//   a0 = A[g][c0,c0+1], a1 = A[g+8][c0,c0+1], a2 = A[g][c0+8,c0+9], a3 = A[g+8][c0+8,c0+9]
__global__ void wprep_kernel(const float* __restrict__ w) {
    int i = blockIdx.x * 256 + threadIdx.x;      // < 36864
    int lane = i & 31;
    int k16  = (i >> 5) & 3;
    int mt16 = (i >> 7) & 15;
    int kt   = i >> 11;
    int g  = lane >> 2;
    int c0 = (lane & 3) * 2;
    int rs = kt >> 1, chalf = kt & 1;
    unsigned hh[4];
#pragma unroll
    for (int p = 0; p < 4; ++p) {
        int row  = mt16 * 16 + g + ((p & 1) ? 8 : 0);
        int colb = c0 + ((p >> 1) ? 8 : 0);
        int cg   = chalf * 64 + k16 * 16 + colb;     // input channel of first half
        float f0 = w[row * 1152 + cg * 9 + rs];
        float f1 = w[row * 1152 + (cg + 1) * 9 + rs];
        unsigned lo = __half_as_ushort(__float2half(f0));
        unsigned hi = __half_as_ushort(__float2half(f1));
        hh[p] = lo | (hi << 16);
    }
    g_wf[i] = make_uint4(hh[0], hh[1], hh[2], hh[3]);
}

__global__ void xprep_kernel(const float* __restrict__ x) {
    __shared__ float t[32][33];
    const int n  = blockIdx.z;
    const int c0 = blockIdx.y * 32;
    const int p0 = blockIdx.x * 32;
    const int tx = threadIdx.x, ty = threadIdx.y;   // 32 x 8
    const float* src = x + ((size_t)n * C_IN + c0) * PIX + p0;
#pragma unroll
    for (int i = 0; i < 4; ++i) {
        int c = ty + i * 8;
        t[c][tx] = src[(size_t)c * PIX + tx];
    }
    __syncthreads();
#pragma unroll
    for (int i = 0; i < 4; ++i) {
        int pr = ty + i * 8;
        g_xt[((size_t)n * PIX + p0 + pr) * C_IN + c0 + tx] = __float2half(t[tx][pr]);
    }
}

// ---------------- main conv kernel ----------------
__global__ __launch_bounds__(NTHREADS, 2)
void conv_mma_fp16_kernel(const float* __restrict__ bias, float* __restrict__ out) {
    extern __shared__ char smem[];
    const uint32_t sbase = smem_u32(smem);
    const int tid = threadIdx.x;
    const int wid = tid >> 5;
    const int l   = tid & 31;
    const int pixBase = blockIdx.x * BN;
    const int mBase   = blockIdx.y * BM;
    const int wy = wid & 1;            // M half (64 rows)
    const int wx = wid >> 1;           // N quarter (32 pixels)

    // ---- per-thread B-row geometry: thread pair owns pixel row tid>>1 ----
    const int brow = tid >> 1;          // 0..127
    const int bhr  = tid & 1;           // half-row (64B)
    const int p    = pixBase + brow;
    const int bn   = p / PIX;
    const int brem = p - bn * PIX;
    const int bh   = brem / HW;
    const int bw   = brem - bh * HW;
    const size_t bimg = (size_t)bn * PIX;

    // ---- B stage issue (cp.async, zero-fill OOB) ----
    auto issueB = [&](int kt) {
        const int st = kt % 3;
        const int rs = kt >> 1, chalf = kt & 1;
        const int r = rs / 3, s = rs - r * 3;
        const int ih = bh + r - 1, iw = bw + s - 1;
        const bool valid = ((unsigned)ih < (unsigned)HW) && ((unsigned)iw < (unsigned)HW);
        const size_t eb = valid ? ((bimg + (size_t)ih * HW + iw) * C_IN + chalf * 64 + bhr * 32)
                                : 0;
        const int ssz = valid ? 16 : 0;
        const uint4* bsrc = (const uint4*)(g_xt + eb);
#pragma unroll
        for (int j = 0; j < 4; ++j) {
            uint32_t dst = sbase + B_OFF(st) +
                           sw128((uint32_t)(brow * 128 + bhr * 64 + j * 16));
            cp16(dst, bsrc + j, ssz);
        }
        asm volatile("cp.async.commit_group;" ::: "memory");
    };

    // ---- A fragment LDG (registers, double-buffered) ----
    const int mt16base = (mBase >> 4) + wy * 4;
    uint4 bufA[2][4];
    auto prefA = [&](int kt, int k16, int buf) {
#pragma unroll
        for (int mt = 0; mt < 4; ++mt)
            bufA[buf][mt] = __ldg(&g_wf[((kt * 16 + mt16base + mt) * 4 + k16) * 32 + l]);
    };

    float acc[4][4][4];
#pragma unroll
    for (int i = 0; i < 4; ++i)
#pragma unroll
        for (int j = 0; j < 4; ++j)
#pragma unroll
            for (int q = 0; q < 4; ++q)
                acc[i][j][q] = 0.0f;

    issueB(0);
    issueB(1);
    prefA(0, 0, 0);

    // B fragment lane addressing (ldmatrix x4 canonical, validated)
    const int b_n       = wx * 32 + (l & 7) + ((l >> 4) << 3);
    const uint32_t b_kb = (uint32_t)((l >> 3) & 1) * 16;

    int cur = 0;
    for (int kt = 0; kt < NKT; ++kt) {
        const int st = kt % 3;
        if (kt == NKT - 1) asm volatile("cp.async.wait_group 0;" ::: "memory");
        else               asm volatile("cp.async.wait_group 1;" ::: "memory");
        __syncthreads();
        if (kt + 2 < NKT) issueB(kt + 2);   // overlaps with compute below

        const uint32_t bB = sbase + B_OFF(st);

#pragma unroll
        for (int k16 = 0; k16 < 4; ++k16) {
            const int nxt = cur ^ 1;
            if (k16 < 3)            prefA(kt, k16 + 1, nxt);
            else if (kt + 1 < NKT)  prefA(kt + 1, 0, nxt);

            uint32_t bf[2][4];
            const uint32_t kb = (uint32_t)k16 * 32;
#pragma unroll
            for (int np = 0; np < 2; ++np)
                ldsm4(bf[np], bB + sw128((uint32_t)((b_n + np * 16) * 128) + kb + b_kb));
#pragma unroll
            for (int mt = 0; mt < 4; ++mt) {
                const uint32_t* a = (const uint32_t*)&bufA[cur][mt];
#pragma unroll
                for (int nt = 0; nt < 4; ++nt)
                    mma_fp16(acc[mt][nt], a, &bf[nt >> 1][(nt & 1) * 2]);
            }
            cur = nxt;
        }
    }

    // ---- epilogue: C frag -> NCHW out (+bias). 8-pixel groups stay in-image. ----
#pragma unroll
    for (int mt = 0; mt < 4; ++mt) {
        const int ch0 = mBase + wy * 64 + mt * 16 + (l >> 2);
        const float bv0 = __ldg(&bias[ch0]);
        const float bv1 = __ldg(&bias[ch0 + 8]);
#pragma unroll
        for (int nt = 0; nt < 4; ++nt) {
            const int p0  = pixBase + wx * 32 + nt * 8 + (l & 3) * 2;
            const int on  = p0 / PIX;
            const int pin = p0 - on * PIX;
            float* o = out + ((size_t)on * K_OUT + ch0) * PIX + pin;
            float2 v0, v1;
            v0.x = acc[mt][nt][0] + bv0; v0.y = acc[mt][nt][1] + bv0;
            v1.x = acc[mt][nt][2] + bv1; v1.y = acc[mt][nt][3] + bv1;
            *(float2*)o             = v0;
            *(float2*)(o + 8 * PIX) = v1;
        }
    }
}

// ---------------- launch ----------------
extern "C" void kernel_launch(void* const* d_in, const int* in_sizes, int n_in,
                              void* d_out, int out_size) {
    const float* x    = (const float*)d_in[0];
    const float* wgt  = (const float*)d_in[1];
    const float* bias = (const float*)d_in[2];
    float* out        = (float*)d_out;

    cudaFuncSetAttribute(conv_mma_fp16_kernel,
                         cudaFuncAttributeMaxDynamicSharedMemorySize, SMEM_TOTAL);

    wprep_kernel<<<(NKT * 16 * 4 * 32) / 256, 256>>>(wgt);   // 144 blocks
    {
        dim3 g(PIX / 32, C_IN / 32, N_IMG);   // (98, 4, 32)
        dim3 b(32, 8);
        xprep_kernel<<<g, b>>>(x);
    }
    conv_mma_fp16_kernel<<<dim3(NPIX / BN, K_OUT / BM), NTHREADS, SMEM_TOTAL>>>(bias, out);
}